// round 14
// baseline (speedup 1.0000x reference)
#include <cuda_runtime.h>
#include <cuda_bf16.h>

// Problem constants (fixed by the reference)
#define NN      100000      // nodes
#define FF      32          // feats
#define CC      16          // classes
#define EE      1600000     // edges
#define EMB_DIM 6
#define HID     9
#define DEPTH   10
#define DIFF    0.9f
#define ODIFF   0.1f        // 1 - DIFF

#define NF  (NN * FF)
#define NF4 (NF / 4)        // float4 elements per u buffer

// ---------------- device scratch (no allocs allowed) ----------------
__device__ int    g_cnt[NN];
__device__ int    g_cur[NN];
__device__ int    g_rowptr[NN + 1];
__device__ int    g_col[EE];
__device__ float  g_invdeg[NN];
__device__ float  g_isd[NN];   // rsqrt(max(deg,1))
__device__ float  g_sqd[NN];   // sqrt(max(deg,1))
__device__ float4 g_u0v[NF4];  // fp32 u buffers (row = 32 floats = 128B)
__device__ float4 g_uav[NF4];
__device__ float4 g_ubv[NF4];

__device__ __forceinline__ float* bufv(int sel) {
    return (sel == 0) ? (float*)g_u0v : (sel == 1) ? (float*)g_uav : (float*)g_ubv;
}

// ---------------- kernels ----------------

// degree count, 4 edges per thread via int4 (EE % 4 == 0)
__global__ void k_count(const int* __restrict__ edges) {
    int t = blockIdx.x * blockDim.x + threadIdx.x;
    if (t >= EE / 4) return;
    int4 d4 = __ldg(&reinterpret_cast<const int4*>(edges + EE)[t]);
    if ((unsigned)d4.x < (unsigned)NN) atomicAdd(&g_cnt[d4.x], 1);
    if ((unsigned)d4.y < (unsigned)NN) atomicAdd(&g_cnt[d4.y], 1);
    if ((unsigned)d4.z < (unsigned)NN) atomicAdd(&g_cnt[d4.z], 1);
    if ((unsigned)d4.w < (unsigned)NN) atomicAdd(&g_cnt[d4.w], 1);
}

// single-block exclusive scan of g_cnt -> g_rowptr, plus per-node scalars
__global__ void k_scan() {
    const int T = 1024;
    int tid = threadIdx.x;
    int chunk = (NN + T - 1) / T;                 // 98
    int beg = tid * chunk;
    int end = beg + chunk; if (end > NN) end = NN;
    if (beg > NN) beg = NN;

    int sum = 0;
    for (int i = beg; i < end; i++) sum += g_cnt[i];

    __shared__ int sh[T];
    sh[tid] = sum;
    __syncthreads();
    for (int off = 1; off < T; off <<= 1) {
        int v = (tid >= off) ? sh[tid - off] : 0;
        __syncthreads();
        sh[tid] += v;
        __syncthreads();
    }
    int run = (tid == 0) ? 0 : sh[tid - 1];       // exclusive prefix
    for (int i = beg; i < end; i++) {
        g_rowptr[i] = run;
        int c = g_cnt[i];
        run += c;
        float d   = (c > 0) ? (float)c : 1.0f;
        float isd = rsqrtf(d);
        g_invdeg[i] = 1.0f / d;
        g_isd[i]    = isd;
        g_sqd[i]    = sqrtf(d);
    }
    if (tid == T - 1) g_rowptr[NN] = run;         // == EE
}

// u0 = x * rsqrt(deg) (scalars already computed by k_scan)
__global__ void k_prep(const float* __restrict__ x) {
    int idx = blockIdx.x * blockDim.x + threadIdx.x;
    if (idx >= NF) return;
    int n = idx >> 5;
    ((float*)g_u0v)[idx] = x[idx] * g_isd[n];
}

// CSR fill, 4 edges per thread via int4
__global__ void k_fill(const int* __restrict__ edges) {
    int t = blockIdx.x * blockDim.x + threadIdx.x;
    if (t >= EE / 4) return;
    int4 s4 = __ldg(&reinterpret_cast<const int4*>(edges)[t]);
    int4 d4 = __ldg(&reinterpret_cast<const int4*>(edges + EE)[t]);
    if ((unsigned)d4.x < (unsigned)NN && (unsigned)s4.x < (unsigned)NN)
        g_col[g_rowptr[d4.x] + atomicAdd(&g_cur[d4.x], 1)] = s4.x;
    if ((unsigned)d4.y < (unsigned)NN && (unsigned)s4.y < (unsigned)NN)
        g_col[g_rowptr[d4.y] + atomicAdd(&g_cur[d4.y], 1)] = s4.y;
    if ((unsigned)d4.z < (unsigned)NN && (unsigned)s4.z < (unsigned)NN)
        g_col[g_rowptr[d4.z] + atomicAdd(&g_cur[d4.z], 1)] = s4.z;
    if ((unsigned)d4.w < (unsigned)NN && (unsigned)s4.w < (unsigned)NN)
        g_col[g_rowptr[d4.w] + atomicAdd(&g_cur[d4.w], 1)] = s4.w;
}

// One warp per dst node, lane = feature (LDG.32: one 128B row per warp
// instruction = 1 L1tex wavefront, no intra-LDG replays). Neighbor indices:
// one coalesced idx load (lane l = slot l, covers deg<=32), broadcast via
// shfl. Gather = 16-deep unrolled uniformly-predicated batch (16 independent
// loads in flight/warp); slots 16..31 in a second guarded batch; deg>32 loops.
__global__ void __launch_bounds__(256) k_conv(int in_sel, int out_sel) {
    const float* __restrict__ u_in  = bufv(in_sel);
    float* __restrict__       u_out = bufv(out_sel);

    int node = (blockIdx.x * blockDim.x + threadIdx.x) >> 5;
    if (node >= NN) return;
    int lane = threadIdx.x & 31;

    int beg = g_rowptr[node];
    int deg = g_rowptr[node + 1] - beg;

    // coalesced index load: lane l holds neighbor slot l (0 if beyond deg)
    int myidx = (lane < deg) ? __ldg(&g_col[beg + lane]) : 0;

    float acc = 0.0f;
    #pragma unroll
    for (int k = 0; k < 16; k++) {
        int s = __shfl_sync(0xffffffffu, myidx, k);
        float v = 0.0f;
        if (k < deg) v = __ldg(&u_in[s * 32 + lane]);   // warp-uniform predicate
        acc += v;
    }
    if (deg > 16) {
        #pragma unroll
        for (int k = 16; k < 32; k++) {
            int s = __shfl_sync(0xffffffffu, myidx, k);
            float v = 0.0f;
            if (k < deg) v = __ldg(&u_in[s * 32 + lane]);
            acc += v;
        }
        // rare: deg > 32
        for (int b = 32; b < deg; b += 32) {
            int mi = (b + lane < deg) ? __ldg(&g_col[beg + b + lane]) : 0;
            int m = deg - b; if (m > 32) m = 32;
            for (int k = 0; k < m; k++) {
                int s = __shfl_sync(0xffffffffu, mi, k);
                acc += __ldg(&u_in[s * 32 + lane]);
            }
        }
    }

    float w  = DIFF * g_invdeg[node];
    float h0 = __ldg(&((const float*)g_u0v)[node * 32 + lane]);
    u_out[node * 32 + lane] = fmaf(w, acc, ODIFF * h0);
}

// per-(node,feature) MLP applied elementwise, with rescale in/out of u-space.
// Reads g_ubv, writes new u0 (= mlp_out * isd) into g_u0v.
__global__ void k_mlp(const float* __restrict__ emb,
                      const float* __restrict__ W1,
                      const float* __restrict__ b1,
                      const float* __restrict__ W2,
                      const float* __restrict__ b2) {
    __shared__ float sA[HID];           // W1 row 0
    __shared__ float sW2[HID];
    __shared__ float sC[FF][HID];       // b1[j] + sum_d emb[f,d]*W1[1+d,j]
    __shared__ float sB2;

    for (int t = threadIdx.x; t < FF * HID; t += blockDim.x) {
        int f = t / HID, j = t % HID;
        float c = b1[j];
        #pragma unroll
        for (int d = 0; d < EMB_DIM; d++)
            c += emb[f * EMB_DIM + d] * W1[(1 + d) * HID + j];
        sC[f][j] = c;
    }
    if (threadIdx.x < HID) {
        sA[threadIdx.x]  = W1[threadIdx.x];      // row 0
        sW2[threadIdx.x] = W2[threadIdx.x];
    }
    if (threadIdx.x == 0) sB2 = b2[0];
    __syncthreads();

    int idx = blockIdx.x * blockDim.x + threadIdx.x;
    if (idx >= NF) return;
    int n = idx >> 5;
    int f = idx & 31;
    float t = ((const float*)g_ubv)[idx] * g_sqd[n];
    float r = sB2;
    #pragma unroll
    for (int j = 0; j < HID; j++) {
        float h = fmaf(sA[j], t, sC[f][j]);
        r = fmaf(sW2[j], fmaxf(h, 0.0f), r);
    }
    ((float*)g_u0v)[idx] = r * g_isd[n];
}

// out[n,c] = bout[c] + sum_k (ub[n,k]*sqd[n]) * Wout[k,c]
__global__ void k_out(const float* __restrict__ Wout,
                      const float* __restrict__ bout,
                      float* __restrict__ out) {
    __shared__ float sW[FF * CC];
    __shared__ float sb[CC];
    for (int t = threadIdx.x; t < FF * CC; t += blockDim.x) sW[t] = Wout[t];
    if (threadIdx.x < CC) sb[threadIdx.x] = bout[threadIdx.x];
    __syncthreads();

    int tid = blockIdx.x * blockDim.x + threadIdx.x;
    if (tid >= NN * CC) return;
    int n = tid >> 4;
    int c = tid & 15;
    float sd = g_sqd[n];
    const float* u = (const float*)g_ubv;
    float acc = sb[c];
    #pragma unroll
    for (int k = 0; k < FF; k++)
        acc = fmaf(u[n * 32 + k] * sd, sW[k * CC + c], acc);
    out[tid] = acc;
}

// ---------------- launch ----------------

extern "C" void kernel_launch(void* const* d_in, const int* in_sizes, int n_in,
                              void* d_out, int out_size) {
    const float* x     = (const float*)d_in[0];
    const int*   edges = (const int*)d_in[1];       // int32 per harness dtype contract
    const float* emb   = (const float*)d_in[2];
    const float* W1    = (const float*)d_in[3];
    const float* b1    = (const float*)d_in[4];
    const float* W2    = (const float*)d_in[5];
    const float* b2    = (const float*)d_in[6];
    const float* Wout  = (const float*)d_in[7];
    const float* bout  = (const float*)d_in[8];
    float* out = (float*)d_out;

    const int TB = 256;
    int gE4 = (EE / 4 + TB - 1) / TB;
    int gNF = (NF + TB - 1) / TB;
    int gW  = (NN * 32 + TB - 1) / TB;   // warp-per-node grid
    int gNC = (NN * CC + TB - 1) / TB;

    // CSR build: counters zeroed via async memset, int4-vectorized passes
    void* cntp = nullptr; cudaGetSymbolAddress(&cntp, g_cnt);
    void* curp = nullptr; cudaGetSymbolAddress(&curp, g_cur);
    cudaMemsetAsync(cntp, 0, NN * sizeof(int));
    cudaMemsetAsync(curp, 0, NN * sizeof(int));
    k_count<<<gE4, TB>>>(edges);
    k_scan<<<1, 1024>>>();
    k_prep<<<gNF, TB>>>(x);
    k_fill<<<gE4, TB>>>(edges);

    // diffuse 1: u starts at u0 (sel 0); 10 conv steps ping-pong ua(1)/ub(2) -> ends in ub
    k_conv<<<gW, TB>>>(0, 1);
    for (int i = 1; i < DEPTH; i++) {
        int in_sel  = (i & 1) ? 1 : 2;
        int out_sel = (i & 1) ? 2 : 1;
        k_conv<<<gW, TB>>>(in_sel, out_sel);
    }

    // per-element MLP (reads g_ubv, writes new u0)
    k_mlp<<<gNF, TB>>>(emb, W1, b1, W2, b2);

    // diffuse 2
    k_conv<<<gW, TB>>>(0, 1);
    for (int i = 1; i < DEPTH; i++) {
        int in_sel  = (i & 1) ? 1 : 2;
        int out_sel = (i & 1) ? 2 : 1;
        k_conv<<<gW, TB>>>(in_sel, out_sel);
    }

    // output GEMM
    k_out<<<gNC, TB>>>(Wout, bout, out);
}

// round 16
// speedup vs baseline: 1.1105x; 1.1105x over previous
#include <cuda_runtime.h>
#include <cuda_bf16.h>

// Problem constants (fixed by the reference)
#define NN      100000      // nodes
#define FF      32          // feats
#define CC      16          // classes
#define EE      1600000     // edges
#define EMB_DIM 6
#define HID     9
#define DEPTH   10
#define DIFF    0.9f
#define ODIFF   0.1f        // 1 - DIFF

#define NF  (NN * FF)
#define NF4 (NF / 4)        // float4 elements per u buffer

// ---------------- device scratch (no allocs allowed) ----------------
__device__ int    g_cnt2[2 * NN];      // [0,NN)=degree count, [NN,2NN)=fill cursor
__device__ int    g_rowptr[NN + 1];
__device__ int    g_col[EE];
__device__ float  g_invdeg[NN];
__device__ float  g_isd[NN];   // rsqrt(max(deg,1))
__device__ float  g_sqd[NN];   // sqrt(max(deg,1))
__device__ float4 g_u0v[NF4];  // fp32 u buffers (row = 32 floats = 128B)
__device__ float4 g_uav[NF4];
__device__ float4 g_ubv[NF4];

__device__ __forceinline__ float4* bufv(int sel) {
    return (sel == 0) ? g_u0v : (sel == 1) ? g_uav : g_ubv;
}

// ---------------- kernels ----------------

// degree count, 4 edges per thread via int4 (EE % 4 == 0)
__global__ void k_count(const int* __restrict__ edges) {
    int t = blockIdx.x * blockDim.x + threadIdx.x;
    if (t >= EE / 4) return;
    int4 d4 = __ldg(&reinterpret_cast<const int4*>(edges + EE)[t]);
    if ((unsigned)d4.x < (unsigned)NN) atomicAdd(&g_cnt2[d4.x], 1);
    if ((unsigned)d4.y < (unsigned)NN) atomicAdd(&g_cnt2[d4.y], 1);
    if ((unsigned)d4.z < (unsigned)NN) atomicAdd(&g_cnt2[d4.z], 1);
    if ((unsigned)d4.w < (unsigned)NN) atomicAdd(&g_cnt2[d4.w], 1);
}

// single-block exclusive scan of counts -> g_rowptr, plus per-node scalars
__global__ void k_scan() {
    const int T = 1024;
    int tid = threadIdx.x;
    int chunk = (NN + T - 1) / T;                 // 98
    int beg = tid * chunk;
    int end = beg + chunk; if (end > NN) end = NN;
    if (beg > NN) beg = NN;

    int sum = 0;
    for (int i = beg; i < end; i++) sum += g_cnt2[i];

    __shared__ int sh[T];
    sh[tid] = sum;
    __syncthreads();
    for (int off = 1; off < T; off <<= 1) {
        int v = (tid >= off) ? sh[tid - off] : 0;
        __syncthreads();
        sh[tid] += v;
        __syncthreads();
    }
    int run = (tid == 0) ? 0 : sh[tid - 1];       // exclusive prefix
    for (int i = beg; i < end; i++) {
        g_rowptr[i] = run;
        int c = g_cnt2[i];
        run += c;
        float d   = (c > 0) ? (float)c : 1.0f;
        float isd = rsqrtf(d);
        g_invdeg[i] = 1.0f / d;
        g_isd[i]    = isd;
        g_sqd[i]    = sqrtf(d);
    }
    if (tid == T - 1) g_rowptr[NN] = run;         // == EE
}

// Fused CSR fill (4 edges per thread via int4) + u0 = x*isd (float4 per thread).
// Grid sized for NF/4 threads; first EE/4 threads also handle edges.
__global__ void k_fillprep(const int* __restrict__ edges,
                           const float* __restrict__ x) {
    int t = blockIdx.x * blockDim.x + threadIdx.x;
    if (t < EE / 4) {
        int4 s4 = __ldg(&reinterpret_cast<const int4*>(edges)[t]);
        int4 d4 = __ldg(&reinterpret_cast<const int4*>(edges + EE)[t]);
        int* cur = g_cnt2 + NN;
        if ((unsigned)d4.x < (unsigned)NN && (unsigned)s4.x < (unsigned)NN)
            g_col[g_rowptr[d4.x] + atomicAdd(&cur[d4.x], 1)] = s4.x;
        if ((unsigned)d4.y < (unsigned)NN && (unsigned)s4.y < (unsigned)NN)
            g_col[g_rowptr[d4.y] + atomicAdd(&cur[d4.y], 1)] = s4.y;
        if ((unsigned)d4.z < (unsigned)NN && (unsigned)s4.z < (unsigned)NN)
            g_col[g_rowptr[d4.z] + atomicAdd(&cur[d4.z], 1)] = s4.z;
        if ((unsigned)d4.w < (unsigned)NN && (unsigned)s4.w < (unsigned)NN)
            g_col[g_rowptr[d4.w] + atomicAdd(&cur[d4.w], 1)] = s4.w;
    }
    if (t < NF4) {
        int n = t >> 3;                            // 8 float4 per 32-float row
        float isd = g_isd[n];
        float4 xv = __ldg(&reinterpret_cast<const float4*>(x)[t]);
        g_u0v[t] = make_float4(xv.x * isd, xv.y * isd, xv.z * isd, xv.w * isd);
    }
}

// one warp per dst node; 4 groups of 8 lanes; group g gathers neighbor j+g
// as 8x float4 (full 128B row per group). Butterfly-combine groups at end.
// u_out[n,:] = 0.9 * invdeg[n] * sum_{s in N(n)} u_in[s,:] + 0.1 * u0[n,:]
__global__ void __launch_bounds__(256) k_conv(int in_sel, int out_sel) {
    const float4* __restrict__ u_in  = bufv(in_sel);
    float4* __restrict__       u_out = bufv(out_sel);

    int gwarp = (blockIdx.x * blockDim.x + threadIdx.x) >> 5;
    if (gwarp >= NN) return;
    int lane = threadIdx.x & 31;
    int sub  = lane >> 3;      // neighbor group 0..3
    int fl   = lane & 7;       // float4 slot within row 0..7

    int beg = g_rowptr[gwarp];
    int end = g_rowptr[gwarp + 1];

    float4 acc = make_float4(0.f, 0.f, 0.f, 0.f);
    int j = beg + sub;
    // main: 16 neighbors per iteration (4 per group), 4 independent LDG.128/lane
    for (; j + 12 < end; j += 16) {
        int s0 = __ldg(&g_col[j]);
        int s1 = __ldg(&g_col[j + 4]);
        int s2 = __ldg(&g_col[j + 8]);
        int s3 = __ldg(&g_col[j + 12]);
        float4 v0 = __ldg(&u_in[s0 * 8 + fl]);
        float4 v1 = __ldg(&u_in[s1 * 8 + fl]);
        float4 v2 = __ldg(&u_in[s2 * 8 + fl]);
        float4 v3 = __ldg(&u_in[s3 * 8 + fl]);
        acc.x += v0.x + v1.x + v2.x + v3.x;
        acc.y += v0.y + v1.y + v2.y + v3.y;
        acc.z += v0.z + v1.z + v2.z + v3.z;
        acc.w += v0.w + v1.w + v2.w + v3.w;
    }
    // tail: each group advances by 4, self-predicated
    for (; j < end; j += 4) {
        int s = __ldg(&g_col[j]);
        float4 v = __ldg(&u_in[s * 8 + fl]);
        acc.x += v.x; acc.y += v.y; acc.z += v.z; acc.w += v.w;
    }

    // combine the 4 group partials (lanes with equal fl across groups)
    #pragma unroll
    for (int off = 8; off < 32; off <<= 1) {
        acc.x += __shfl_xor_sync(0xffffffffu, acc.x, off);
        acc.y += __shfl_xor_sync(0xffffffffu, acc.y, off);
        acc.z += __shfl_xor_sync(0xffffffffu, acc.z, off);
        acc.w += __shfl_xor_sync(0xffffffffu, acc.w, off);
    }

    if (sub == 0) {
        float  w  = DIFF * g_invdeg[gwarp];
        float4 h0 = __ldg(&g_u0v[gwarp * 8 + fl]);
        float4 r;
        r.x = fmaf(w, acc.x, ODIFF * h0.x);
        r.y = fmaf(w, acc.y, ODIFF * h0.y);
        r.z = fmaf(w, acc.z, ODIFF * h0.z);
        r.w = fmaf(w, acc.w, ODIFF * h0.w);
        u_out[gwarp * 8 + fl] = r;
    }
}

// per-(node,feature) MLP applied elementwise, with rescale in/out of u-space.
// Reads g_ubv, writes new u0 (= mlp_out * isd) into g_u0v.
__global__ void k_mlp(const float* __restrict__ emb,
                      const float* __restrict__ W1,
                      const float* __restrict__ b1,
                      const float* __restrict__ W2,
                      const float* __restrict__ b2) {
    __shared__ float sA[HID];           // W1 row 0
    __shared__ float sW2[HID];
    __shared__ float sC[FF][HID];       // b1[j] + sum_d emb[f,d]*W1[1+d,j]
    __shared__ float sB2;

    for (int t = threadIdx.x; t < FF * HID; t += blockDim.x) {
        int f = t / HID, j = t % HID;
        float c = b1[j];
        #pragma unroll
        for (int d = 0; d < EMB_DIM; d++)
            c += emb[f * EMB_DIM + d] * W1[(1 + d) * HID + j];
        sC[f][j] = c;
    }
    if (threadIdx.x < HID) {
        sA[threadIdx.x]  = W1[threadIdx.x];      // row 0
        sW2[threadIdx.x] = W2[threadIdx.x];
    }
    if (threadIdx.x == 0) sB2 = b2[0];
    __syncthreads();

    int idx = blockIdx.x * blockDim.x + threadIdx.x;
    if (idx >= NF) return;
    int n = idx >> 5;
    int f = idx & 31;
    float t = ((const float*)g_ubv)[idx] * g_sqd[n];
    float r = sB2;
    #pragma unroll
    for (int j = 0; j < HID; j++) {
        float h = fmaf(sA[j], t, sC[f][j]);
        r = fmaf(sW2[j], fmaxf(h, 0.0f), r);
    }
    ((float*)g_u0v)[idx] = r * g_isd[n];
}

// out[n,c] = bout[c] + sum_k (ub[n,k]*sqd[n]) * Wout[k,c]
__global__ void k_out(const float* __restrict__ Wout,
                      const float* __restrict__ bout,
                      float* __restrict__ out) {
    __shared__ float sW[FF * CC];
    __shared__ float sb[CC];
    for (int t = threadIdx.x; t < FF * CC; t += blockDim.x) sW[t] = Wout[t];
    if (threadIdx.x < CC) sb[threadIdx.x] = bout[threadIdx.x];
    __syncthreads();

    int tid = blockIdx.x * blockDim.x + threadIdx.x;
    if (tid >= NN * CC) return;
    int n = tid >> 4;
    int c = tid & 15;
    float sd = g_sqd[n];
    const float* u = (const float*)g_ubv;
    float acc = sb[c];
    #pragma unroll
    for (int k = 0; k < FF; k++)
        acc = fmaf(u[n * 32 + k] * sd, sW[k * CC + c], acc);
    out[tid] = acc;
}

// ---------------- launch ----------------

extern "C" void kernel_launch(void* const* d_in, const int* in_sizes, int n_in,
                              void* d_out, int out_size) {
    const float* x     = (const float*)d_in[0];
    const int*   edges = (const int*)d_in[1];       // int32 per harness dtype contract
    const float* emb   = (const float*)d_in[2];
    const float* W1    = (const float*)d_in[3];
    const float* b1    = (const float*)d_in[4];
    const float* W2    = (const float*)d_in[5];
    const float* b2    = (const float*)d_in[6];
    const float* Wout  = (const float*)d_in[7];
    const float* bout  = (const float*)d_in[8];
    float* out = (float*)d_out;

    const int TB = 256;
    int gE4 = (EE / 4 + TB - 1) / TB;
    int gFP = (NF4 + TB - 1) / TB;       // covers both fill (EE/4) and prep (NF/4)
    int gNF = (NF + TB - 1) / TB;
    int gW  = (NN * 32 + TB - 1) / TB;   // warp-per-node grid
    int gNC = (NN * CC + TB - 1) / TB;

    // pre-phase in exactly 4 launches: memset, count, scan, fill+prep
    void* cntp = nullptr; cudaGetSymbolAddress(&cntp, g_cnt2);
    cudaMemsetAsync(cntp, 0, 2 * NN * sizeof(int));
    k_count<<<gE4, TB>>>(edges);
    k_scan<<<1, 1024>>>();
    k_fillprep<<<gFP, TB>>>(edges, x);

    // diffuse 1: u starts at u0 (sel 0); 10 conv steps ping-pong ua(1)/ub(2) -> ends in ub
    k_conv<<<gW, TB>>>(0, 1);
    for (int i = 1; i < DEPTH; i++) {
        int in_sel  = (i & 1) ? 1 : 2;
        int out_sel = (i & 1) ? 2 : 1;
        k_conv<<<gW, TB>>>(in_sel, out_sel);
    }

    // per-element MLP (reads g_ubv, writes new u0)
    k_mlp<<<gNF, TB>>>(emb, W1, b1, W2, b2);

    // diffuse 2
    k_conv<<<gW, TB>>>(0, 1);
    for (int i = 1; i < DEPTH; i++) {
        int in_sel  = (i & 1) ? 1 : 2;
        int out_sel = (i & 1) ? 2 : 1;
        k_conv<<<gW, TB>>>(in_sel, out_sel);
    }

    // output GEMM
    k_out<<<gNC, TB>>>(Wout, bout, out);
}

// round 17
// speedup vs baseline: 1.2939x; 1.1652x over previous
#include <cuda_runtime.h>
#include <cuda_fp16.h>

// Problem constants (fixed by the reference)
#define NN      100000      // nodes
#define FF      32          // feats
#define CC      16          // classes
#define EE      1600000     // edges
#define EMB_DIM 6
#define HID     9
#define DEPTH   10
#define DIFF    0.9f
#define ODIFF   0.1f        // 1 - DIFF

#define NF   (NN * FF)
#define COLP (EE + 3 * NN)  // padded col capacity (rows padded to multiple of 4)

// ---------------- device scratch (no allocs allowed) ----------------
__device__ int    g_cnt2[2 * NN];        // [0,NN)=true degree, [NN,2NN)=fill cursor
__device__ int    g_rowptr[NN + 1];      // prefix of PADDED (mult-of-4) degrees
__device__ int    g_col[COLP];
__device__ float  g_invdeg[NN];
__device__ float  g_isd[NN];             // rsqrt(max(deg,1))
__device__ float  g_sqd[NN];             // sqrt(max(deg,1))
// fp16 u buffers: row = 32 halfs = 64B = 4 uint4. Row NN = sentinel zero row
// (zero-initialized, never written) used for CSR padding slots.
__device__ uint4  g_h0[(NN + 1) * 4];
__device__ uint4  g_ha[(NN + 1) * 4];
__device__ uint4  g_hb[(NN + 1) * 4];
__device__ float  g_uf[NF];              // fp32 result of each diffuse phase

__device__ __forceinline__ uint4* hbuf(int sel) {
    return (sel == 0) ? g_h0 : (sel == 1) ? g_ha : g_hb;
}

// ---------------- kernels ----------------

// degree count, 4 edges per thread via int4 (EE % 4 == 0)
__global__ void k_count(const int* __restrict__ edges) {
    int t = blockIdx.x * blockDim.x + threadIdx.x;
    if (t >= EE / 4) return;
    int4 d4 = __ldg(&reinterpret_cast<const int4*>(edges + EE)[t]);
    if ((unsigned)d4.x < (unsigned)NN) atomicAdd(&g_cnt2[d4.x], 1);
    if ((unsigned)d4.y < (unsigned)NN) atomicAdd(&g_cnt2[d4.y], 1);
    if ((unsigned)d4.z < (unsigned)NN) atomicAdd(&g_cnt2[d4.z], 1);
    if ((unsigned)d4.w < (unsigned)NN) atomicAdd(&g_cnt2[d4.w], 1);
}

// single-block exclusive scan of PADDED counts -> g_rowptr, plus per-node scalars
__global__ void k_scan() {
    const int T = 1024;
    int tid = threadIdx.x;
    int chunk = (NN + T - 1) / T;                 // 98
    int beg = tid * chunk;
    int end = beg + chunk; if (end > NN) end = NN;
    if (beg > NN) beg = NN;

    int sum = 0;
    for (int i = beg; i < end; i++) sum += (g_cnt2[i] + 3) & ~3;

    __shared__ int sh[T];
    sh[tid] = sum;
    __syncthreads();
    for (int off = 1; off < T; off <<= 1) {
        int v = (tid >= off) ? sh[tid - off] : 0;
        __syncthreads();
        sh[tid] += v;
        __syncthreads();
    }
    int run = (tid == 0) ? 0 : sh[tid - 1];       // exclusive prefix (padded)
    for (int i = beg; i < end; i++) {
        g_rowptr[i] = run;
        int c = g_cnt2[i];
        run += (c + 3) & ~3;
        float d   = (c > 0) ? (float)c : 1.0f;
        float isd = rsqrtf(d);
        g_invdeg[i] = 1.0f / d;
        g_isd[i]    = isd;
        g_sqd[i]    = sqrtf(d);
    }
    if (tid == T - 1) g_rowptr[NN] = run;
}

// Fused: CSR fill (int4, 4 edges/thread) + padding-slot fill (sentinel NN)
// + u0 = x*isd packed to fp16 (8 halfs per thread).
__global__ void k_fillprep(const int* __restrict__ edges,
                           const float* __restrict__ x) {
    int t = blockIdx.x * blockDim.x + threadIdx.x;
    if (t < EE / 4) {
        int4 s4 = __ldg(&reinterpret_cast<const int4*>(edges)[t]);
        int4 d4 = __ldg(&reinterpret_cast<const int4*>(edges + EE)[t]);
        int* cur = g_cnt2 + NN;
        if ((unsigned)d4.x < (unsigned)NN && (unsigned)s4.x < (unsigned)NN)
            g_col[g_rowptr[d4.x] + atomicAdd(&cur[d4.x], 1)] = s4.x;
        if ((unsigned)d4.y < (unsigned)NN && (unsigned)s4.y < (unsigned)NN)
            g_col[g_rowptr[d4.y] + atomicAdd(&cur[d4.y], 1)] = s4.y;
        if ((unsigned)d4.z < (unsigned)NN && (unsigned)s4.z < (unsigned)NN)
            g_col[g_rowptr[d4.z] + atomicAdd(&cur[d4.z], 1)] = s4.z;
        if ((unsigned)d4.w < (unsigned)NN && (unsigned)s4.w < (unsigned)NN)
            g_col[g_rowptr[d4.w] + atomicAdd(&cur[d4.w], 1)] = s4.w;
    } else if (t < EE / 4 + NN) {
        int n = t - EE / 4;
        int c = g_cnt2[n];
        int cpad = (c + 3) & ~3;
        int base = g_rowptr[n];
        for (int k = c; k < cpad; k++) g_col[base + k] = NN;   // zero-row sentinel
    } else if (t < EE / 4 + NN + NF / 8) {
        int u = t - (EE / 4 + NN);        // uint4 index into g_h0
        int n = u >> 2;
        float isd = g_isd[n];
        const float4* xp = reinterpret_cast<const float4*>(x) + u * 2;
        float4 xa = __ldg(xp);
        float4 xb = __ldg(xp + 1);
        uint4 o;
        half2* oh = reinterpret_cast<half2*>(&o);
        oh[0] = __floats2half2_rn(xa.x * isd, xa.y * isd);
        oh[1] = __floats2half2_rn(xa.z * isd, xa.w * isd);
        oh[2] = __floats2half2_rn(xb.x * isd, xb.y * isd);
        oh[3] = __floats2half2_rn(xb.z * isd, xb.w * isd);
        g_h0[u] = o;
    }
}

// One warp per dst node; 4 groups of 8 lanes; lane owns 8B (uint2 = 2 half2)
// of the 64B fp16 row. Group g processes whole QUADS of contiguous neighbors
// (one aligned int4 idx load per 4 neighbors; padding slots hit the zero row).
// HADD2 accumulation; one fp32 convert per node; 2-stage shfl combine.
// OUT_HALF: write fp16 row to hbuf(out_sel); else fp32 row to g_uf.
template <bool OUT_HALF>
__global__ void __launch_bounds__(256) k_conv(int in_sel, int out_sel) {
    const uint2* __restrict__ u_in = reinterpret_cast<const uint2*>(hbuf(in_sel));

    int node = (blockIdx.x * blockDim.x + threadIdx.x) >> 5;
    if (node >= NN) return;
    int lane = threadIdx.x & 31;
    int grp  = lane >> 3;     // quad group 0..3
    int sl   = lane & 7;      // uint2 slot within row 0..7

    int beg = g_rowptr[node];                       // multiple of 4
    int Q   = (g_rowptr[node + 1] - beg) >> 2;      // padded quad count
    const int4* qidx = reinterpret_cast<const int4*>(g_col) + (beg >> 2);

    half2 a0 = __floats2half2_rn(0.f, 0.f);
    half2 a1 = __floats2half2_rn(0.f, 0.f);
    for (int q = grp; q < Q; q += 4) {
        int4 s = __ldg(&qidx[q]);
        uint2 v0 = __ldg(&u_in[s.x * 8 + sl]);
        uint2 v1 = __ldg(&u_in[s.y * 8 + sl]);
        uint2 v2 = __ldg(&u_in[s.z * 8 + sl]);
        uint2 v3 = __ldg(&u_in[s.w * 8 + sl]);
        a0 = __hadd2(a0, *reinterpret_cast<half2*>(&v0.x));
        a1 = __hadd2(a1, *reinterpret_cast<half2*>(&v0.y));
        a0 = __hadd2(a0, *reinterpret_cast<half2*>(&v1.x));
        a1 = __hadd2(a1, *reinterpret_cast<half2*>(&v1.y));
        a0 = __hadd2(a0, *reinterpret_cast<half2*>(&v2.x));
        a1 = __hadd2(a1, *reinterpret_cast<half2*>(&v2.y));
        a0 = __hadd2(a0, *reinterpret_cast<half2*>(&v3.x));
        a1 = __hadd2(a1, *reinterpret_cast<half2*>(&v3.y));
    }

    float2 f0 = __half22float2(a0);
    float2 f1 = __half22float2(a1);
    float acc[4] = {f0.x, f0.y, f1.x, f1.y};
    #pragma unroll
    for (int off = 8; off <= 16; off <<= 1) {
        #pragma unroll
        for (int k = 0; k < 4; k++)
            acc[k] += __shfl_xor_sync(0xffffffffu, acc[k], off);
    }

    if (grp == 0) {
        float w = DIFF * __ldg(&g_invdeg[node]);
        uint2 h0v = __ldg(&reinterpret_cast<const uint2*>(g_h0)[node * 8 + sl]);
        float2 h00 = __half22float2(*reinterpret_cast<half2*>(&h0v.x));
        float2 h01 = __half22float2(*reinterpret_cast<half2*>(&h0v.y));
        float r0 = fmaf(w, acc[0], ODIFF * h00.x);
        float r1 = fmaf(w, acc[1], ODIFF * h00.y);
        float r2 = fmaf(w, acc[2], ODIFF * h01.x);
        float r3 = fmaf(w, acc[3], ODIFF * h01.y);
        if (OUT_HALF) {
            uint2 o;
            *reinterpret_cast<half2*>(&o.x) = __floats2half2_rn(r0, r1);
            *reinterpret_cast<half2*>(&o.y) = __floats2half2_rn(r2, r3);
            reinterpret_cast<uint2*>(hbuf(out_sel))[node * 8 + sl] = o;
        } else {
            reinterpret_cast<float4*>(g_uf)[node * 8 + sl] =
                make_float4(r0, r1, r2, r3);
        }
    }
}

// per-(node,feature) MLP elementwise, rescaled in/out of u-space.
// Reads g_uf (fp32), writes new u0 (fp16) into g_h0. Two feats per thread.
__global__ void k_mlp(const float* __restrict__ emb,
                      const float* __restrict__ W1,
                      const float* __restrict__ b1,
                      const float* __restrict__ W2,
                      const float* __restrict__ b2) {
    __shared__ float sA[HID];           // W1 row 0
    __shared__ float sW2[HID];
    __shared__ float sC[FF][HID];       // b1[j] + sum_d emb[f,d]*W1[1+d,j]
    __shared__ float sB2;

    for (int t = threadIdx.x; t < FF * HID; t += blockDim.x) {
        int f = t / HID, j = t % HID;
        float c = b1[j];
        #pragma unroll
        for (int d = 0; d < EMB_DIM; d++)
            c += emb[f * EMB_DIM + d] * W1[(1 + d) * HID + j];
        sC[f][j] = c;
    }
    if (threadIdx.x < HID) {
        sA[threadIdx.x]  = W1[threadIdx.x];      // row 0
        sW2[threadIdx.x] = W2[threadIdx.x];
    }
    if (threadIdx.x == 0) sB2 = b2[0];
    __syncthreads();

    int idx2 = blockIdx.x * blockDim.x + threadIdx.x;   // half2 index
    if (idx2 >= NF / 2) return;
    int n  = idx2 >> 4;
    int f0 = (idx2 & 15) * 2;
    float sq  = g_sqd[n];
    float isd = g_isd[n];
    float2 tv = reinterpret_cast<const float2*>(g_uf)[idx2];
    float t0 = tv.x * sq, t1 = tv.y * sq;
    float r0 = sB2, r1 = sB2;
    #pragma unroll
    for (int j = 0; j < HID; j++) {
        float h0 = fmaf(sA[j], t0, sC[f0][j]);
        float h1 = fmaf(sA[j], t1, sC[f0 + 1][j]);
        r0 = fmaf(sW2[j], fmaxf(h0, 0.0f), r0);
        r1 = fmaf(sW2[j], fmaxf(h1, 0.0f), r1);
    }
    reinterpret_cast<half2*>(g_h0)[idx2] = __floats2half2_rn(r0 * isd, r1 * isd);
}

// out[n,c] = bout[c] + sum_k (g_uf[n,k]*sqd[n]) * Wout[k,c]
__global__ void k_out(const float* __restrict__ Wout,
                      const float* __restrict__ bout,
                      float* __restrict__ out) {
    __shared__ float sW[FF * CC];
    __shared__ float sb[CC];
    for (int t = threadIdx.x; t < FF * CC; t += blockDim.x) sW[t] = Wout[t];
    if (threadIdx.x < CC) sb[threadIdx.x] = bout[threadIdx.x];
    __syncthreads();

    int tid = blockIdx.x * blockDim.x + threadIdx.x;
    if (tid >= NN * CC) return;
    int n = tid >> 4;
    int c = tid & 15;
    float sd = g_sqd[n];
    float acc = sb[c];
    #pragma unroll
    for (int k = 0; k < FF; k++)
        acc = fmaf(g_uf[n * 32 + k] * sd, sW[k * CC + c], acc);
    out[tid] = acc;
}

// ---------------- launch ----------------

static void diffuse(int gW, int TB) {
    // step 1: u0(fp16, sel 0) -> ha(1)
    k_conv<true><<<gW, TB>>>(0, 1);
    // steps 2..9: ping-pong ha(1)/hb(2)
    for (int i = 2; i < DEPTH; i++) {
        int in_sel  = (i & 1) ? 2 : 1;
        int out_sel = (i & 1) ? 1 : 2;
        k_conv<true><<<gW, TB>>>(in_sel, out_sel);
    }
    // step 10: in = ha(1) (step 9 wrote sel 1) -> fp32 g_uf
    k_conv<false><<<gW, TB>>>(1, 0 /*unused*/);
}

extern "C" void kernel_launch(void* const* d_in, const int* in_sizes, int n_in,
                              void* d_out, int out_size) {
    const float* x     = (const float*)d_in[0];
    const int*   edges = (const int*)d_in[1];       // int32 per harness dtype contract
    const float* emb   = (const float*)d_in[2];
    const float* W1    = (const float*)d_in[3];
    const float* b1    = (const float*)d_in[4];
    const float* W2    = (const float*)d_in[5];
    const float* b2    = (const float*)d_in[6];
    const float* Wout  = (const float*)d_in[7];
    const float* bout  = (const float*)d_in[8];
    float* out = (float*)d_out;

    const int TB = 256;
    int gE4 = (EE / 4 + TB - 1) / TB;
    int nFP = EE / 4 + NN + NF / 8;               // fill + pad + u0-pack threads
    int gFP = (nFP + TB - 1) / TB;
    int gW  = (NN * 32 + TB - 1) / TB;            // warp-per-node conv grid
    int gH2 = (NF / 2 + TB - 1) / TB;             // half2-element grid (mlp)
    int gNC = (NN * CC + TB - 1) / TB;

    // pre-phase: memset, count, scan, fill+pad+prep (4 launches)
    void* cntp = nullptr; cudaGetSymbolAddress(&cntp, g_cnt2);
    cudaMemsetAsync(cntp, 0, 2 * NN * sizeof(int));
    k_count<<<gE4, TB>>>(edges);
    k_scan<<<1, 1024>>>();
    k_fillprep<<<gFP, TB>>>(edges, x);

    // diffuse 1 -> g_uf (fp32)
    diffuse(gW, TB);

    // per-element MLP (reads g_uf, writes new fp16 u0 into g_h0)
    k_mlp<<<gH2, TB>>>(emb, W1, b1, W2, b2);

    // diffuse 2 -> g_uf (fp32)
    diffuse(gW, TB);

    // output GEMM
    k_out<<<gNC, TB>>>(Wout, bout, out);
}